// round 5
// baseline (speedup 1.0000x reference)
#include <cuda_runtime.h>
#include <cuda_bf16.h>
#include <cstdint>

// ---------------- problem constants ----------------
constexpr int NU   = 4096;
constexpr int NS   = 8192;
constexpr int ND   = 32;
constexpr int NREG = 128;
#define GA_CONST 0.1

// ---------------- tiling ----------------
constexpr int TSB = 256;                 // items per block (8 warps x 32)
constexpr int TUB = 64;                  // users per block
constexpr int SBLK = NS / TSB;           // 32
constexpr int MAIN = SBLK * (NU / TUB);  // 2048
constexpr int REGB = 128;
constexpr int GRIDN = MAIN + REGB;       // 2176

// streaming pipeline
constexpr int GU        = 8;                     // users per group
constexpr int NGRP      = TUB / GU;              // 8 groups
constexpr int ARR_BYTES = GU * TSB * 4;          // 8192 per array per group
constexpr int GRP_BYTES = 3 * ARR_BYTES;         // 24576

// dynamic smem layout
constexpr int OFF_ITEM   = 0;                    // 256*17*4 = 17408
constexpr int OFF_USER   = 17408;                // 4096
constexpr int OFF_STREAM = 21504;                // 2 * 24576 = 49152 (1KB aligned)
constexpr int OFF_FULL   = 70656;                // 2 mbarriers
constexpr int OFF_EMPTY  = 70672;                // 2 mbarriers
constexpr int OFF_RED    = 70688;                // 8 floats
constexpr int OFF_DACC   = 70720;                // 8 doubles
constexpr int OFF_LAST   = 70784;                // int
constexpr int SMEM_TOTAL = 70912;

// k_pre sizing
constexpr int CONV_F4 = (NU * ND + NS * ND) / 4;   // 98304
constexpr int CONV_BLOCKS = CONV_F4 / 256;         // 384
constexpr int PRE_GRID = CONV_BLOCKS + NU / 256;   // +16

// ---------------- device scratch ----------------
__device__ double       g_acc  = 0.0;
__device__ unsigned int g_done = 0u;
__device__ float        g_rsum[NREG * ND];
__device__ float        g_rcnt[NREG];
__device__ unsigned     g_ue[NU * ND / 2];
__device__ unsigned     g_ie[NS * ND / 2];

static __device__ __forceinline__ __nv_bfloat162 asbf2(unsigned v) {
    return *reinterpret_cast<__nv_bfloat162*>(&v);
}
static __device__ __forceinline__ uint32_t smem_u32(const void* p) {
    uint32_t a;
    asm("{ .reg .u64 t; cvta.to.shared.u64 t, %1; cvt.u32.u64 %0, t; }" : "=r"(a) : "l"(p));
    return a;
}
#define MBARRIER_INIT(a, c) \
    asm volatile("mbarrier.init.shared.b64 [%0], %1;" :: "r"(a), "r"(c) : "memory")
#define MBARRIER_ARRIVE(a) \
    asm volatile("mbarrier.arrive.shared.b64 _, [%0];" :: "r"(a) : "memory")
#define MBARRIER_EXPECT_TX(a, n) \
    asm volatile("mbarrier.arrive.expect_tx.shared.b64 _, [%0], %1;" :: "r"(a), "r"(n) : "memory")
#define MBARRIER_WAIT(a, ph) do {                                              \
    uint32_t _m = (a), _p = (ph), _d;                                          \
    asm volatile("{\n\t.reg .pred p;\n\t"                                      \
        "mbarrier.try_wait.parity.acquire.cta.shared::cta.b64 p, [%1], %2;\n\t"\
        "selp.b32 %0, 1, 0, p;\n\t}" : "=r"(_d) : "r"(_m), "r"(_p) : "memory");\
    if (!_d) {                                                                 \
        asm volatile("{\n\t.reg .pred P1;\n\t"                                 \
            "W_%=:\n\t"                                                        \
            "mbarrier.try_wait.parity.acquire.cta.shared::cta.b64 P1, [%0], %1, 0x989680;\n\t" \
            "@P1 bra.uni D_%=;\n\tbra.uni W_%=;\n\tD_%=:\n\t}"                 \
            :: "r"(_m), "r"(_p) : "memory");                                   \
    }                                                                          \
} while (0)
#define BULK_G2S(dst, src, bytes, mbar) \
    asm volatile("cp.async.bulk.shared::cta.global.mbarrier::complete_tx::bytes [%0], [%1], %2, [%3];" \
                 :: "r"(dst), "l"(src), "r"(bytes), "r"(mbar) : "memory")

// ---------------- kernel 1: bf16 convert + region segment sums ----------------
__global__ void k_pre(const float* __restrict__ user_emb,
                      const float* __restrict__ item_emb,
                      const int*   __restrict__ ridx) {
    const int b = blockIdx.x, t = threadIdx.x;
    if (b < CONV_BLOCKS) {
        int idx = b * 256 + t;
        constexpr int UF4 = NU * ND / 4;
        float4 f;
        unsigned* dst;
        if (idx < UF4) {
            f = ((const float4*)user_emb)[idx];
            dst = &g_ue[idx * 2];
        } else {
            int v = idx - UF4;
            f = ((const float4*)item_emb)[v];
            dst = &g_ie[v * 2];
        }
        __nv_bfloat162 h0 = __floats2bfloat162_rn(f.x, f.y);
        __nv_bfloat162 h1 = __floats2bfloat162_rn(f.z, f.w);
        dst[0] = *reinterpret_cast<unsigned*>(&h0);
        dst[1] = *reinterpret_cast<unsigned*>(&h1);
    } else {
        const int rb = b - CONV_BLOCKS;
        const int warp = t >> 5, lane = t & 31;
        const int u0 = rb * 256 + warp * 32;
#pragma unroll 4
        for (int k = 0; k < 32; ++k) {
            int u = u0 + k;
            int r = __ldg(ridx + u);
            float e = user_emb[(size_t)u * ND + lane];
            atomicAdd(&g_rsum[r * ND + lane], e);
            if (lane == 0) atomicAdd(&g_rcnt[r], 1.0f);
        }
    }
}

// ---------------- kernel 2: fused loss, bulk-async streamed ----------------
__global__ __launch_bounds__(256, 3)
void k_main(const float* __restrict__ user_emb,
            const int*   __restrict__ mask,
            const float* __restrict__ tq,
            const float* __restrict__ wgt,
            const int*   __restrict__ ridx,
            float*       __restrict__ out)
{
    extern __shared__ __align__(1024) char dsm[];
    const uint32_t sb = smem_u32(dsm);
    const int tid  = threadIdx.x;
    const int b    = blockIdx.x;
    const int warp = tid >> 5, lane = tid & 31;
    double blockpart = 0.0;

    if (b < MAIN) {
        const int sbase = (b & (SBLK - 1)) * TSB;
        const int ubase = (b >> 5) * TUB;

        unsigned* s_item = (unsigned*)(dsm + OFF_ITEM);
        unsigned* s_user = (unsigned*)(dsm + OFF_USER);

        // stage embeddings (L2-resident bf16)
        {
            const unsigned* gi = g_ie + (size_t)sbase * (ND / 2);
#pragma unroll
            for (int i = 0; i < 16; ++i) {
                int w = tid + i * 256;
                s_item[(w >> 4) * 17 + (w & 15)] = gi[w];
            }
            const unsigned* gu = g_ue + (size_t)ubase * (ND / 2);
#pragma unroll
            for (int i = 0; i < 4; ++i) s_user[tid + i * 256] = gu[tid + i * 256];
        }
        if (tid == 0) {
            MBARRIER_INIT(sb + OFF_FULL,      1);
            MBARRIER_INIT(sb + OFF_FULL + 8,  1);
            MBARRIER_INIT(sb + OFF_EMPTY,     256);
            MBARRIER_INIT(sb + OFF_EMPTY + 8, 256);
        }
        __syncthreads();

        // producer helper: stage group g into ring slot (g&1)
        auto prefetch = [&](int g) {
            const int st = g & 1;
            const uint32_t mb = sb + OFF_FULL + st * 8;
            MBARRIER_EXPECT_TX(mb, GRP_BYTES);
            const uint32_t dst0 = sb + OFF_STREAM + st * GRP_BYTES;
            const size_t rowbase = (size_t)(ubase + g * GU) * NS + sbase;
#pragma unroll
            for (int u = 0; u < GU; ++u) {
                const size_t off = rowbase + (size_t)u * NS;
                BULK_G2S(dst0 +                 u * 1024, (const void*)(mask + off), 1024, mb);
                BULK_G2S(dst0 + ARR_BYTES     + u * 1024, (const void*)(tq   + off), 1024, mb);
                BULK_G2S(dst0 + 2 * ARR_BYTES + u * 1024, (const void*)(wgt  + off), 1024, mb);
            }
        };
        if (tid == 0) { prefetch(0); prefetch(1); }

        // item fragment (bf16x2 x16)
        const int irow = warp * 32 + lane;
        __nv_bfloat162 a[16];
        {
            const unsigned* p = &s_item[irow * 17];
#pragma unroll
            for (int k = 0; k < 16; ++k) a[k] = asbf2(p[k]);
        }
        const __nv_bfloat162 zero2 = __floats2bfloat162_rn(0.f, 0.f);

        float lsum = 0.0f;
#pragma unroll 1
        for (int g = 0; g < NGRP; ++g) {
            const int st = g & 1, ph = (g >> 1) & 1;
            MBARRIER_WAIT(sb + OFF_FULL + st * 8, ph);

            const char*  base = dsm + OFF_STREAM + st * GRP_BYTES;
            const int*   sm_m = (const int*)  base;
            const float* sm_t = (const float*)(base + ARR_BYTES);
            const float* sm_w = (const float*)(base + 2 * ARR_BYTES);

#pragma unroll 2
            for (int u = 0; u < GU; ++u) {
                const int   m = sm_m[u * TSB + irow];
                const float t = sm_t[u * TSB + irow];
                const float w = sm_w[u * TSB + irow];

                const uint4* q = (const uint4*)&s_user[(g * GU + u) * 16];
                uint4 q0 = q[0], q1 = q[1], q2 = q[2], q3 = q[3];
                unsigned uw[16] = {q0.x,q0.y,q0.z,q0.w, q1.x,q1.y,q1.z,q1.w,
                                   q2.x,q2.y,q2.z,q2.w, q3.x,q3.y,q3.z,q3.w};
                __nv_bfloat162 ca = zero2, cb = zero2;
#pragma unroll
                for (int k = 0; k < 16; k += 2) {
                    ca = __hfma2(a[k],     asbf2(uw[k]),     ca);
                    cb = __hfma2(a[k + 1], asbf2(uw[k + 1]), cb);
                }
                __nv_bfloat162 s2 = __hadd2(ca, cb);
                float dot = __low2float(s2) + __high2float(s2);
                float p = m ? dot : 0.0f;
                float d = p - t;
                lsum = fmaf(w * d, d, lsum);
            }

            MBARRIER_ARRIVE(sb + OFF_EMPTY + st * 8);
            if (tid == 0 && g + 2 < NGRP) {
                MBARRIER_WAIT(sb + OFF_EMPTY + st * 8, ph);   // all consumed slot st
                prefetch(g + 2);
            }
        }

        // block reduce
#pragma unroll
        for (int o = 16; o; o >>= 1) lsum += __shfl_xor_sync(0xffffffffu, lsum, o);
        float* s_red = (float*)(dsm + OFF_RED);
        if (lane == 0) s_red[warp] = lsum;
        __syncthreads();
        if (tid == 0) {
            float s = 0.0f;
#pragma unroll
            for (int i = 0; i < 8; ++i) s += s_red[i];
            blockpart = (double)s;
        }
    } else {
        // ============ region LOO-deviation: warp = 4 users, lane = dim ============
        const int rb = b - MAIN;
        const int u0 = rb * 32 + warp * 4;
        double wacc = 0.0;
#pragma unroll
        for (int k = 0; k < 4; ++k) {
            int u = u0 + k;
            int r = ridx[u];
            float cnt = g_rcnt[r];
            float e   = user_emb[(size_t)u * ND + lane];
            float loo = (g_rsum[r * ND + lane] - e) / fmaxf(cnt - 1.0f, 1.0f);
            float dev = fabsf(e - loo);
#pragma unroll
            for (int o = 16; o; o >>= 1) dev += __shfl_xor_sync(0xffffffffu, dev, o);
            if (lane == 0 && cnt > 1.0f) wacc += (double)dev;
        }
        double* s_dacc = (double*)(dsm + OFF_DACC);
        if (lane == 0) s_dacc[warp] = wacc;
        __syncthreads();
        if (tid == 0) {
            double t = 0.0;
#pragma unroll
            for (int i = 0; i < 8; ++i) t += s_dacc[i];
            blockpart = GA_CONST * t;
        }
    }

    // ============ epilogue: accumulate; last block writes + resets ============
    int* s_last = (int*)(dsm + OFF_LAST);
    if (tid == 0) {
        atomicAdd(&g_acc, blockpart);
        __threadfence();
        unsigned old = atomicAdd(&g_done, 1u);
        *s_last = (old == (unsigned)(GRIDN - 1));
    }
    __syncthreads();
    if (*s_last) {
        for (int i = tid; i < NREG * ND; i += 256) g_rsum[i] = 0.0f;
        if (tid < NREG) g_rcnt[tid] = 0.0f;
        __syncthreads();
        if (tid == 0) {
            __threadfence();
            out[0] = (float)g_acc;
            g_acc  = 0.0;
            g_done = 0u;
        }
    }
}

// ---------------- launch ----------------
extern "C" void kernel_launch(void* const* d_in, const int* in_sizes, int n_in,
                              void* d_out, int out_size) {
    const float* user_emb = (const float*)d_in[0];
    const float* item_emb = (const float*)d_in[1];
    const int*   mask     = (const int*)  d_in[2];
    const float* tq       = (const float*)d_in[3];
    const float* wgt      = (const float*)d_in[4];
    const int*   ridx     = (const int*)  d_in[5];

    cudaFuncSetAttribute(k_main, cudaFuncAttributeMaxDynamicSharedMemorySize, SMEM_TOTAL);
    k_pre<<<PRE_GRID, 256>>>(user_emb, item_emb, ridx);
    k_main<<<GRIDN, 256, SMEM_TOTAL>>>(user_emb, mask, tq, wgt, ridx, (float*)d_out);
}

// round 6
// speedup vs baseline: 1.1410x; 1.1410x over previous
#include <cuda_runtime.h>
#include <cuda_bf16.h>
#include <cstdint>

// ---------------- problem constants ----------------
constexpr int NU   = 4096;
constexpr int NS   = 8192;
constexpr int ND   = 32;
constexpr int NREG = 128;
#define GA_CONST 0.1

// ---------------- tiling ----------------
constexpr int TSB = 256;                 // items per block (8 warps x 32 items)
constexpr int TUB = 64;                  // users per block
constexpr int SBLK = NS / TSB;           // 32
constexpr int MAIN = SBLK * (NU / TUB);  // 2048
constexpr int REGB = 128;                // region-loss blocks
constexpr int GRIDN = MAIN + REGB;       // 2176

// k_pre sizing
constexpr int CONV_F4 = (NU * ND + NS * ND) / 4;   // 98304 float4s
constexpr int CONV_BLOCKS = CONV_F4 / 256;         // 384
constexpr int PRE_GRID = CONV_BLOCKS + NU / 256;   // +16

// ---------------- device scratch ----------------
__device__ double       g_acc  = 0.0;
__device__ unsigned int g_done = 0u;
__device__ float        g_rsum[NREG * ND];
__device__ float        g_rcnt[NREG];
__device__ unsigned     g_ue[NU * ND / 2];          // user emb bf16x2 words
__device__ unsigned     g_ie[NS * ND / 2];          // item emb bf16x2 words

static __device__ __forceinline__ __nv_bfloat162 asbf2(unsigned v) {
    return *reinterpret_cast<__nv_bfloat162*>(&v);
}

// ---------------- kernel 1: bf16 convert + region segment sums ----------------
__global__ void k_pre(const float* __restrict__ user_emb,
                      const float* __restrict__ item_emb,
                      const int*   __restrict__ ridx) {
    const int b = blockIdx.x, t = threadIdx.x;
    if (b < CONV_BLOCKS) {
        int idx = b * 256 + t;                       // float4 id
        constexpr int UF4 = NU * ND / 4;             // 32768
        float4 f;
        unsigned* dst;
        if (idx < UF4) {
            f = ((const float4*)user_emb)[idx];
            dst = &g_ue[idx * 2];
        } else {
            int v = idx - UF4;
            f = ((const float4*)item_emb)[v];
            dst = &g_ie[v * 2];
        }
        __nv_bfloat162 h0 = __floats2bfloat162_rn(f.x, f.y);
        __nv_bfloat162 h1 = __floats2bfloat162_rn(f.z, f.w);
        dst[0] = *reinterpret_cast<unsigned*>(&h0);
        dst[1] = *reinterpret_cast<unsigned*>(&h1);
    } else {
        // region segment sums: warp handles 32 users, lane = dim
        const int rb = b - CONV_BLOCKS;
        const int warp = t >> 5, lane = t & 31;
        const int u0 = rb * 256 + warp * 32;
#pragma unroll 4
        for (int k = 0; k < 32; ++k) {
            int u = u0 + k;
            int r = __ldg(ridx + u);
            float e = user_emb[(size_t)u * ND + lane];
            atomicAdd(&g_rsum[r * ND + lane], e);
            if (lane == 0) atomicAdd(&g_rcnt[r], 1.0f);
        }
    }
}

// ---------------- kernel 2: fused loss (register double-buffered streams) ----------------
__global__ __launch_bounds__(256, 3)
void k_main(const float* __restrict__ user_emb,
            const int*   __restrict__ mask,
            const float* __restrict__ tq,
            const float* __restrict__ wgt,
            const int*   __restrict__ ridx,
            float*       __restrict__ out)
{
    __shared__ unsigned s_item[TSB * 17];   // item words, row stride 17
    __shared__ unsigned s_user[TUB * 16];   // user words, dense rows
    __shared__ float    s_red[8];
    __shared__ double   s_dacc[8];
    __shared__ int      s_last;

    const int tid  = threadIdx.x;
    const int b    = blockIdx.x;
    const int warp = tid >> 5, lane = tid & 31;
    double blockpart = 0.0;

    if (b < MAIN) {
        // ============ main tile: 256 items x 64 users ============
        const int sbase = (b & (SBLK - 1)) * TSB;
        const int ubase = (b >> 5) * TUB;

        // stage embeddings (L2-resident bf16)
        {
            const unsigned* gi = g_ie + (size_t)sbase * (ND / 2);
#pragma unroll
            for (int i = 0; i < 16; ++i) {
                int w = tid + i * 256;
                s_item[(w >> 4) * 17 + (w & 15)] = gi[w];
            }
            const unsigned* gu = g_ue + (size_t)ubase * (ND / 2);
#pragma unroll
            for (int i = 0; i < 4; ++i) s_user[tid + i * 256] = gu[tid + i * 256];
        }
        __syncthreads();

        // item fragment: this lane's item row (16 bf16x2 words)
        const int irow = warp * 32 + lane;
        __nv_bfloat162 a[16];
        {
            const unsigned* p = &s_item[irow * 17];
#pragma unroll
            for (int k = 0; k < 16; ++k) a[k] = asbf2(p[k]);
        }

        const size_t base = (size_t)ubase * NS + sbase + irow;
        const int*   mp = mask + base;
        const float* tp = tq   + base;
        const float* wp = wgt  + base;
        const __nv_bfloat162 zero2 = __floats2bfloat162_rn(0.f, 0.f);

        // double-buffered stream registers: while computing group g, group g+1 is in flight
        int   mm[2][4];
        float tt[2][4], ww[2][4];
#pragma unroll
        for (int j = 0; j < 4; ++j) {
            const size_t o = (size_t)j * NS;
            mm[0][j] = __ldcs(mp + o);
            tt[0][j] = __ldcs(tp + o);
            ww[0][j] = __ldcs(wp + o);
        }

        float lsum = 0.0f;
#pragma unroll 4
        for (int ub = 0; ub < TUB; ub += 4) {
            const int cur = (ub >> 2) & 1, nxt = cur ^ 1;
            if (ub + 4 < TUB) {
                const size_t o0 = (size_t)(ub + 4) * NS;
#pragma unroll
                for (int j = 0; j < 4; ++j) {
                    const size_t o = o0 + (size_t)j * NS;
                    mm[nxt][j] = __ldcs(mp + o);
                    tt[nxt][j] = __ldcs(tp + o);
                    ww[nxt][j] = __ldcs(wp + o);
                }
            }
#pragma unroll
            for (int j = 0; j < 4; ++j) {
                const uint4* q = (const uint4*)&s_user[(ub + j) * 16];
                uint4 q0 = q[0], q1 = q[1], q2 = q[2], q3 = q[3];
                unsigned uw[16] = {q0.x,q0.y,q0.z,q0.w, q1.x,q1.y,q1.z,q1.w,
                                   q2.x,q2.y,q2.z,q2.w, q3.x,q3.y,q3.z,q3.w};
                __nv_bfloat162 ca = zero2, cb = zero2;
#pragma unroll
                for (int k = 0; k < 16; k += 2) {
                    ca = __hfma2(a[k],     asbf2(uw[k]),     ca);
                    cb = __hfma2(a[k + 1], asbf2(uw[k + 1]), cb);
                }
                __nv_bfloat162 s2 = __hadd2(ca, cb);
                float dot = __low2float(s2) + __high2float(s2);
                float p = mm[cur][j] ? dot : 0.0f;
                float d = p - tt[cur][j];
                lsum = fmaf(ww[cur][j] * d, d, lsum);
            }
        }

        // block reduce
#pragma unroll
        for (int o = 16; o; o >>= 1) lsum += __shfl_xor_sync(0xffffffffu, lsum, o);
        if (lane == 0) s_red[warp] = lsum;
        __syncthreads();
        if (tid == 0) {
            float s = 0.0f;
#pragma unroll
            for (int i = 0; i < 8; ++i) s += s_red[i];
            blockpart = (double)s;
        }
    } else {
        // ============ region LOO-deviation: warp = 4 users, lane = dim ============
        const int rb = b - MAIN;
        const int u0 = rb * 32 + warp * 4;
        double wacc = 0.0;
#pragma unroll
        for (int k = 0; k < 4; ++k) {
            int u = u0 + k;
            int r = ridx[u];
            float cnt = g_rcnt[r];
            float e   = user_emb[(size_t)u * ND + lane];
            float loo = (g_rsum[r * ND + lane] - e) / fmaxf(cnt - 1.0f, 1.0f);
            float dev = fabsf(e - loo);
#pragma unroll
            for (int o = 16; o; o >>= 1) dev += __shfl_xor_sync(0xffffffffu, dev, o);
            if (lane == 0 && cnt > 1.0f) wacc += (double)dev;
        }
        if (lane == 0) s_dacc[warp] = wacc;
        __syncthreads();
        if (tid == 0) {
            double t = 0.0;
#pragma unroll
            for (int i = 0; i < 8; ++i) t += s_dacc[i];
            blockpart = GA_CONST * t;
        }
    }

    // ============ epilogue: accumulate; last block writes + resets ============
    if (tid == 0) {
        atomicAdd(&g_acc, blockpart);
        __threadfence();
        unsigned old = atomicAdd(&g_done, 1u);
        s_last = (old == (unsigned)(GRIDN - 1));
    }
    __syncthreads();
    if (s_last) {
        for (int i = tid; i < NREG * ND; i += 256) g_rsum[i] = 0.0f;
        if (tid < NREG) g_rcnt[tid] = 0.0f;
        __syncthreads();
        if (tid == 0) {
            __threadfence();
            out[0] = (float)g_acc;
            g_acc  = 0.0;
            g_done = 0u;
        }
    }
}

// ---------------- launch ----------------
extern "C" void kernel_launch(void* const* d_in, const int* in_sizes, int n_in,
                              void* d_out, int out_size) {
    const float* user_emb = (const float*)d_in[0];
    const float* item_emb = (const float*)d_in[1];
    const int*   mask     = (const int*)  d_in[2];
    const float* tq       = (const float*)d_in[3];
    const float* wgt      = (const float*)d_in[4];
    const int*   ridx     = (const int*)  d_in[5];

    k_pre<<<PRE_GRID, 256>>>(user_emb, item_emb, ridx);
    k_main<<<GRIDN, 256>>>(user_emb, mask, tq, wgt, ridx, (float*)d_out);
}

// round 7
// speedup vs baseline: 1.1466x; 1.0050x over previous
#include <cuda_runtime.h>
#include <cuda_bf16.h>
#include <cstdint>

// ---------------- problem constants ----------------
constexpr int NU   = 4096;
constexpr int NS   = 8192;
constexpr int ND   = 32;
constexpr int NREG = 128;
#define GA_CONST 0.1

// ---------------- tiling ----------------
constexpr int TSB = 512;                 // items per block (8 warps x 64)
constexpr int TUB = 32;                  // users per block
constexpr int SBLK = NS / TSB;           // 16
constexpr int MAIN = SBLK * (NU / TUB);  // 2048
constexpr int RSUMB = 16;                // region segment-sum blocks (first)
constexpr int REGB  = 128;               // region-loss blocks (last)
constexpr int GRIDN = RSUMB + MAIN + REGB;   // 2192

// ---------------- device scratch ----------------
__device__ double       g_acc  = 0.0;
__device__ unsigned int g_done = 0u;
__device__ unsigned int g_rsum_done = 0u;
__device__ float        g_rsum[NREG * ND];
__device__ float        g_rcnt[NREG];

static __device__ __forceinline__ __nv_bfloat162 asbf2(unsigned v) {
    return *reinterpret_cast<__nv_bfloat162*>(&v);
}

__global__ __launch_bounds__(256, 3)
void k_all(const float* __restrict__ user_emb,
           const float* __restrict__ item_emb,
           const int*   __restrict__ mask,
           const float* __restrict__ tq,
           const float* __restrict__ wgt,
           const int*   __restrict__ ridx,
           float*       __restrict__ out)
{
    __shared__ unsigned s_item[TSB * 17];   // 512 rows x 16 words, stride 17 (~34.8KB)
    __shared__ unsigned s_user[TUB * 16];   // 2KB
    __shared__ float    s_red[8];
    __shared__ double   s_dacc[8];
    __shared__ int      s_last;

    const int tid  = threadIdx.x;
    const int b    = blockIdx.x;
    const int warp = tid >> 5, lane = tid & 31;
    double blockpart = 0.0;

    if (b < RSUMB) {
        // ============ region segment sums (scheduled first) ============
        const int u0 = b * 256 + warp * 32;
#pragma unroll 4
        for (int k = 0; k < 32; ++k) {
            int u = u0 + k;
            int r = __ldg(ridx + u);
            float e = user_emb[(size_t)u * ND + lane];
            atomicAdd(&g_rsum[r * ND + lane], e);
            if (lane == 0) atomicAdd(&g_rcnt[r], 1.0f);
        }
        __threadfence();
        __syncthreads();
        if (tid == 0) atomicAdd(&g_rsum_done, 1u);
    } else if (b < RSUMB + MAIN) {
        // ============ main tile: 512 items x 32 users ============
        const int b2 = b - RSUMB;
        const int sbase = (b2 & (SBLK - 1)) * TSB;
        const int ubase = (b2 >> 4) * TUB;       // b2 / SBLK

        // stage item tile: fp32 -> bf16 smem (16384 floats, 16 iters)
        {
            const float4* g = (const float4*)(item_emb + (size_t)sbase * ND);
#pragma unroll
            for (int i = 0; i < 16; ++i) {
                int idx = tid + i * 256;          // float4 id
                float4 v = g[idx];
                int f = idx * 4;
                int row = f >> 5, col = (f & 31) >> 1;
                __nv_bfloat162 h0 = __floats2bfloat162_rn(v.x, v.y);
                __nv_bfloat162 h1 = __floats2bfloat162_rn(v.z, v.w);
                unsigned* p = &s_item[row * 17 + col];
                p[0] = *reinterpret_cast<unsigned*>(&h0);
                p[1] = *reinterpret_cast<unsigned*>(&h1);
            }
            const float4* gu = (const float4*)(user_emb + (size_t)ubase * ND);
            {
                int idx = tid;                    // 256 float4s exactly
                float4 v = gu[idx];
                int f = idx * 4;
                int row = f >> 5, col = (f & 31) >> 1;
                __nv_bfloat162 h0 = __floats2bfloat162_rn(v.x, v.y);
                __nv_bfloat162 h1 = __floats2bfloat162_rn(v.z, v.w);
                unsigned* p = &s_user[row * 16 + col];
                p[0] = *reinterpret_cast<unsigned*>(&h0);
                p[1] = *reinterpret_cast<unsigned*>(&h1);
            }
        }
        __syncthreads();

        // item fragments: 2 rows per lane (irow, irow+1)
        const int irow = warp * 64 + lane * 2;
        __nv_bfloat162 a0[16], a1[16];
        {
            const unsigned* r0 = &s_item[irow * 17];
            const unsigned* r1 = r0 + 17;
#pragma unroll
            for (int k = 0; k < 16; ++k) { a0[k] = asbf2(r0[k]); a1[k] = asbf2(r1[k]); }
        }

        const size_t base = (size_t)ubase * NS + sbase + irow;
        const __nv_bfloat162 zero2 = __floats2bfloat162_rn(0.f, 0.f);

        // double-buffered 64-bit stream loads
        int2   mm[2];
        float2 tt[2], ww[2];
        mm[0] = __ldcs((const int2*)  (mask + base));
        tt[0] = __ldcs((const float2*)(tq   + base));
        ww[0] = __ldcs((const float2*)(wgt  + base));

        float lsum = 0.0f;
#pragma unroll 4
        for (int u = 0; u < TUB; ++u) {
            const int cur = u & 1, nxt = cur ^ 1;
            if (u + 1 < TUB) {
                const size_t off = base + (size_t)(u + 1) * NS;
                mm[nxt] = __ldcs((const int2*)  (mask + off));
                tt[nxt] = __ldcs((const float2*)(tq   + off));
                ww[nxt] = __ldcs((const float2*)(wgt  + off));
            }
            const uint4* q = (const uint4*)&s_user[u * 16];
            uint4 q0 = q[0], q1 = q[1], q2 = q[2], q3 = q[3];
            unsigned uw[16] = {q0.x,q0.y,q0.z,q0.w, q1.x,q1.y,q1.z,q1.w,
                               q2.x,q2.y,q2.z,q2.w, q3.x,q3.y,q3.z,q3.w};
            __nv_bfloat162 c0a = zero2, c0b = zero2, c1a = zero2, c1b = zero2;
#pragma unroll
            for (int k = 0; k < 16; k += 2) {
                __nv_bfloat162 ua = asbf2(uw[k]);
                __nv_bfloat162 ub = asbf2(uw[k + 1]);
                c0a = __hfma2(a0[k],     ua, c0a);
                c0b = __hfma2(a0[k + 1], ub, c0b);
                c1a = __hfma2(a1[k],     ua, c1a);
                c1b = __hfma2(a1[k + 1], ub, c1b);
            }
            __nv_bfloat162 s0 = __hadd2(c0a, c0b);
            __nv_bfloat162 s1 = __hadd2(c1a, c1b);
            float dot0 = __low2float(s0) + __high2float(s0);
            float dot1 = __low2float(s1) + __high2float(s1);
            float p0 = mm[cur].x ? dot0 : 0.0f;
            float p1 = mm[cur].y ? dot1 : 0.0f;
            float d0 = p0 - tt[cur].x;
            float d1 = p1 - tt[cur].y;
            lsum = fmaf(ww[cur].x * d0, d0, lsum);
            lsum = fmaf(ww[cur].y * d1, d1, lsum);
        }

        // block reduce
#pragma unroll
        for (int o = 16; o; o >>= 1) lsum += __shfl_xor_sync(0xffffffffu, lsum, o);
        if (lane == 0) s_red[warp] = lsum;
        __syncthreads();
        if (tid == 0) {
            float s = 0.0f;
#pragma unroll
            for (int i = 0; i < 8; ++i) s += s_red[i];
            blockpart = (double)s;
        }
    } else {
        // ============ region LOO-deviation (scheduled last) ============
        if (tid == 0) {
            while (atomicAdd(&g_rsum_done, 0u) < (unsigned)RSUMB) { }
        }
        __syncthreads();
        __threadfence();

        const int rb = b - RSUMB - MAIN;            // 0..127
        const int u0 = rb * 32 + warp * 4;
        double wacc = 0.0;
#pragma unroll
        for (int k = 0; k < 4; ++k) {
            int u = u0 + k;
            int r = ridx[u];
            float cnt = g_rcnt[r];
            float e   = user_emb[(size_t)u * ND + lane];
            float loo = (g_rsum[r * ND + lane] - e) / fmaxf(cnt - 1.0f, 1.0f);
            float dev = fabsf(e - loo);
#pragma unroll
            for (int o = 16; o; o >>= 1) dev += __shfl_xor_sync(0xffffffffu, dev, o);
            if (lane == 0 && cnt > 1.0f) wacc += (double)dev;
        }
        if (lane == 0) s_dacc[warp] = wacc;
        __syncthreads();
        if (tid == 0) {
            double t = 0.0;
#pragma unroll
            for (int i = 0; i < 8; ++i) t += s_dacc[i];
            blockpart = GA_CONST * t;
        }
    }

    // ============ epilogue: accumulate; last block writes + resets ============
    if (tid == 0) {
        atomicAdd(&g_acc, blockpart);
        __threadfence();
        unsigned old = atomicAdd(&g_done, 1u);
        s_last = (old == (unsigned)(GRIDN - 1));
    }
    __syncthreads();
    if (s_last) {
        for (int i = tid; i < NREG * ND; i += 256) g_rsum[i] = 0.0f;
        if (tid < NREG) g_rcnt[tid] = 0.0f;
        __syncthreads();
        if (tid == 0) {
            __threadfence();
            out[0] = (float)g_acc;
            g_acc  = 0.0;
            g_done = 0u;
            g_rsum_done = 0u;
        }
    }
}

// ---------------- launch ----------------
extern "C" void kernel_launch(void* const* d_in, const int* in_sizes, int n_in,
                              void* d_out, int out_size) {
    const float* user_emb = (const float*)d_in[0];
    const float* item_emb = (const float*)d_in[1];
    const int*   mask     = (const int*)  d_in[2];
    const float* tq       = (const float*)d_in[3];
    const float* wgt      = (const float*)d_in[4];
    const int*   ridx     = (const int*)  d_in[5];

    k_all<<<GRIDN, 256>>>(user_emb, item_emb, mask, tq, wgt, ridx, (float*)d_out);
}

// round 8
// speedup vs baseline: 1.1652x; 1.0163x over previous
#include <cuda_runtime.h>
#include <cuda_bf16.h>
#include <cstdint>

// ---------------- problem constants ----------------
constexpr int NU   = 4096;
constexpr int NS   = 8192;
constexpr int ND   = 32;
constexpr int NREG = 128;
#define GA_CONST 0.1

// ---------------- tiling ----------------
constexpr int TSB = 512;                 // items per tile (8 warps x 64)
constexpr int TUB = 32;                  // users per tile
constexpr int SBLK = NS / TSB;           // 16
constexpr int NTILE = SBLK * (NU / TUB); // 2048 tiles
constexpr int WORKERS = 444;             // 148 SMs x 3 CTAs: one wave exactly
constexpr int RSUMB = 16;                // region segment-sum blocks
constexpr int REGB  = 128;               // region-loss blocks
constexpr int GRIDN = RSUMB + REGB + WORKERS;   // 588

// ---------------- device scratch ----------------
__device__ double       g_acc  = 0.0;
__device__ unsigned int g_done = 0u;
__device__ unsigned int g_rsum_done = 0u;
__device__ unsigned int g_tile = 0u;
__device__ float        g_rsum[NREG * ND];
__device__ float        g_rcnt[NREG];

static __device__ __forceinline__ __nv_bfloat162 asbf2(unsigned v) {
    return *reinterpret_cast<__nv_bfloat162*>(&v);
}

__global__ __launch_bounds__(256, 3)
void k_all(const float* __restrict__ user_emb,
           const float* __restrict__ item_emb,
           const int*   __restrict__ mask,
           const float* __restrict__ tq,
           const float* __restrict__ wgt,
           const int*   __restrict__ ridx,
           float*       __restrict__ out)
{
    __shared__ unsigned s_item[TSB * 17];   // ~34.8KB
    __shared__ unsigned s_user[TUB * 16];   // 2KB
    __shared__ float    s_red[8];
    __shared__ double   s_dacc[8];
    __shared__ int      s_tile;
    __shared__ int      s_last;

    const int tid  = threadIdx.x;
    const int b    = blockIdx.x;
    const int warp = tid >> 5, lane = tid & 31;
    double blockpart = 0.0;

    if (b < RSUMB) {
        // ============ region segment sums (first) ============
        const int u0 = b * 256 + warp * 32;
#pragma unroll 4
        for (int k = 0; k < 32; ++k) {
            int u = u0 + k;
            int r = __ldg(ridx + u);
            float e = user_emb[(size_t)u * ND + lane];
            atomicAdd(&g_rsum[r * ND + lane], e);
            if (lane == 0) atomicAdd(&g_rcnt[r], 1.0f);
        }
        __threadfence();
        __syncthreads();
        if (tid == 0) atomicAdd(&g_rsum_done, 1u);
    } else if (b < RSUMB + REGB) {
        // ============ region LOO-deviation ============
        if (tid == 0) {
            while (atomicAdd(&g_rsum_done, 0u) < (unsigned)RSUMB) { }
        }
        __syncthreads();
        __threadfence();

        const int rb = b - RSUMB;                   // 0..127
        const int u0 = rb * 32 + warp * 4;
        double wacc = 0.0;
#pragma unroll
        for (int k = 0; k < 4; ++k) {
            int u = u0 + k;
            int r = ridx[u];
            float cnt = g_rcnt[r];
            float e   = user_emb[(size_t)u * ND + lane];
            float loo = (g_rsum[r * ND + lane] - e) / fmaxf(cnt - 1.0f, 1.0f);
            float dev = fabsf(e - loo);
#pragma unroll
            for (int o = 16; o; o >>= 1) dev += __shfl_xor_sync(0xffffffffu, dev, o);
            if (lane == 0 && cnt > 1.0f) wacc += (double)dev;
        }
        if (lane == 0) s_dacc[warp] = wacc;
        __syncthreads();
        if (tid == 0) {
            double t = 0.0;
#pragma unroll
            for (int i = 0; i < 8; ++i) t += s_dacc[i];
            blockpart = GA_CONST * t;
        }
    } else {
        // ============ persistent main worker: steal 512x32 tiles ============
        float lsum = 0.0f;                          // persists across tiles
        const __nv_bfloat162 zero2 = __floats2bfloat162_rn(0.f, 0.f);

        for (;;) {
            __syncthreads();                        // previous tile fully consumed
            if (tid == 0) s_tile = (int)atomicAdd(&g_tile, 1u);
            __syncthreads();
            const int t = s_tile;
            if (t >= NTILE) break;

            const int sbase = (t & (SBLK - 1)) * TSB;
            const int ubase = (t >> 4) * TUB;

            // stage item tile fp32 -> bf16 (16 float4 iters) + user tile (1 iter)
            {
                const float4* g = (const float4*)(item_emb + (size_t)sbase * ND);
#pragma unroll
                for (int i = 0; i < 16; ++i) {
                    int idx = tid + i * 256;
                    float4 v = g[idx];
                    int f = idx * 4;
                    int row = f >> 5, col = (f & 31) >> 1;
                    __nv_bfloat162 h0 = __floats2bfloat162_rn(v.x, v.y);
                    __nv_bfloat162 h1 = __floats2bfloat162_rn(v.z, v.w);
                    unsigned* p = &s_item[row * 17 + col];
                    p[0] = *reinterpret_cast<unsigned*>(&h0);
                    p[1] = *reinterpret_cast<unsigned*>(&h1);
                }
                const float4* gu = (const float4*)(user_emb + (size_t)ubase * ND);
                float4 v = gu[tid];
                int f = tid * 4;
                int row = f >> 5, col = (f & 31) >> 1;
                __nv_bfloat162 h0 = __floats2bfloat162_rn(v.x, v.y);
                __nv_bfloat162 h1 = __floats2bfloat162_rn(v.z, v.w);
                unsigned* p = &s_user[row * 16 + col];
                p[0] = *reinterpret_cast<unsigned*>(&h0);
                p[1] = *reinterpret_cast<unsigned*>(&h1);
            }
            __syncthreads();

            // item fragments: 2 rows per lane
            const int irow = warp * 64 + lane * 2;
            __nv_bfloat162 a0[16], a1[16];
            {
                const unsigned* r0 = &s_item[irow * 17];
                const unsigned* r1 = r0 + 17;
#pragma unroll
                for (int k = 0; k < 16; ++k) { a0[k] = asbf2(r0[k]); a1[k] = asbf2(r1[k]); }
            }

            const size_t base = (size_t)ubase * NS + sbase + irow;

            int2   mm[2];
            float2 tt[2], ww[2];
            mm[0] = __ldcs((const int2*)  (mask + base));
            tt[0] = __ldcs((const float2*)(tq   + base));
            ww[0] = __ldcs((const float2*)(wgt  + base));

#pragma unroll 4
            for (int u = 0; u < TUB; ++u) {
                const int cur = u & 1, nxt = cur ^ 1;
                if (u + 1 < TUB) {
                    const size_t off = base + (size_t)(u + 1) * NS;
                    mm[nxt] = __ldcs((const int2*)  (mask + off));
                    tt[nxt] = __ldcs((const float2*)(tq   + off));
                    ww[nxt] = __ldcs((const float2*)(wgt  + off));
                }
                const uint4* q = (const uint4*)&s_user[u * 16];
                uint4 q0 = q[0], q1 = q[1], q2 = q[2], q3 = q[3];
                unsigned uw[16] = {q0.x,q0.y,q0.z,q0.w, q1.x,q1.y,q1.z,q1.w,
                                   q2.x,q2.y,q2.z,q2.w, q3.x,q3.y,q3.z,q3.w};
                __nv_bfloat162 c0a = zero2, c0b = zero2, c1a = zero2, c1b = zero2;
#pragma unroll
                for (int k = 0; k < 16; k += 2) {
                    __nv_bfloat162 ua = asbf2(uw[k]);
                    __nv_bfloat162 ub = asbf2(uw[k + 1]);
                    c0a = __hfma2(a0[k],     ua, c0a);
                    c0b = __hfma2(a0[k + 1], ub, c0b);
                    c1a = __hfma2(a1[k],     ua, c1a);
                    c1b = __hfma2(a1[k + 1], ub, c1b);
                }
                __nv_bfloat162 s0 = __hadd2(c0a, c0b);
                __nv_bfloat162 s1 = __hadd2(c1a, c1b);
                float dot0 = __low2float(s0) + __high2float(s0);
                float dot1 = __low2float(s1) + __high2float(s1);
                float p0 = mm[cur].x ? dot0 : 0.0f;
                float p1 = mm[cur].y ? dot1 : 0.0f;
                float d0 = p0 - tt[cur].x;
                float d1 = p1 - tt[cur].y;
                lsum = fmaf(ww[cur].x * d0, d0, lsum);
                lsum = fmaf(ww[cur].y * d1, d1, lsum);
            }
        }

        // one reduction per worker CTA at exit
#pragma unroll
        for (int o = 16; o; o >>= 1) lsum += __shfl_xor_sync(0xffffffffu, lsum, o);
        if (lane == 0) s_red[warp] = lsum;
        __syncthreads();
        if (tid == 0) {
            float s = 0.0f;
#pragma unroll
            for (int i = 0; i < 8; ++i) s += s_red[i];
            blockpart = (double)s;
        }
    }

    // ============ epilogue: accumulate; last block writes + resets ============
    if (tid == 0) {
        atomicAdd(&g_acc, blockpart);
        __threadfence();
        unsigned old = atomicAdd(&g_done, 1u);
        s_last = (old == (unsigned)(GRIDN - 1));
    }
    __syncthreads();
    if (s_last) {
        for (int i = tid; i < NREG * ND; i += 256) g_rsum[i] = 0.0f;
        if (tid < NREG) g_rcnt[tid] = 0.0f;
        __syncthreads();
        if (tid == 0) {
            __threadfence();
            out[0] = (float)g_acc;
            g_acc  = 0.0;
            g_done = 0u;
            g_rsum_done = 0u;
            g_tile = 0u;
        }
    }
}

// ---------------- launch ----------------
extern "C" void kernel_launch(void* const* d_in, const int* in_sizes, int n_in,
                              void* d_out, int out_size) {
    const float* user_emb = (const float*)d_in[0];
    const float* item_emb = (const float*)d_in[1];
    const int*   mask     = (const int*)  d_in[2];
    const float* tq       = (const float*)d_in[3];
    const float* wgt      = (const float*)d_in[4];
    const int*   ridx     = (const int*)  d_in[5];

    k_all<<<GRIDN, 256>>>(user_emb, item_emb, mask, tq, wgt, ridx, (float*)d_out);
}